// round 1
// baseline (speedup 1.0000x reference)
#include <cuda_runtime.h>
#include <cstdint>

#define VOCAB 50257
#define SLEN  2048
#define BATCH 64
#define HDIM  300
#define HPAD  304
#define HALF  150
#define GCHUNK 76            // HPAD / 4 groups
#define NJ    19             // GCHUNK / 4 float4s per lane
#define RNN_THREADS 640      // 20 warps: 20*8 = 160 row slots >= 150
#define RNN_SMEM ((HALF*HPAD + 2*HPAD) * 4)

// Scratch (device globals are the sanctioned allocation-free scratch).
__device__ float g_proj[(size_t)VOCAB * HDIM];   // ~60.3 MB, fits L2 for the gather phase
__device__ float g_pooled[SLEN * HDIM];

// ---------------------------------------------------------------------------
// packed f32x2 helpers (FFMA2 — only reachable via PTX on sm_103a)
// ---------------------------------------------------------------------------
__device__ __forceinline__ unsigned long long fma2(unsigned long long a,
                                                   unsigned long long b,
                                                   unsigned long long c) {
    unsigned long long d;
    asm("fma.rn.f32x2 %0, %1, %2, %3;" : "=l"(d) : "l"(a), "l"(b), "l"(c));
    return d;
}

// ---------------------------------------------------------------------------
// Kernel 0: zero the pooled max buffer (graph replays must re-zero it)
// ---------------------------------------------------------------------------
__global__ void zero_pooled_kernel() {
    int idx = blockIdx.x * blockDim.x + threadIdx.x;
    if (idx < SLEN * HDIM) g_pooled[idx] = 0.f;
}

// ---------------------------------------------------------------------------
// Kernel 1: proj[v, i] = sum_k emb[v,k] * W_ih[i,k] + b_ih[i] + b_hh[i]
// Classic 64x64 tiled fp32 GEMM, 4x4 micro-tiles, KC=16.
// ---------------------------------------------------------------------------
#define PK_KC 16
__global__ void __launch_bounds__(256)
proj_kernel(const float* __restrict__ emb, const float* __restrict__ W_ih,
            const float* __restrict__ b_ih, const float* __restrict__ b_hh)
{
    __shared__ float sA[PK_KC][68];   // [k][m]  (emb tile, transposed)
    __shared__ float sB[PK_KC][68];   // [k][n]  (W_ih tile, transposed)

    const int tid = threadIdx.x;
    const int tx = tid & 15;
    const int ty = tid >> 4;
    const int m0 = blockIdx.x * 64;
    const int n0 = blockIdx.y * 64;

    const int e  = tid * 4;      // each thread loads one float4 per tile
    const int lm = e >> 4;       // 0..63
    const int lk = e & 15;       // 0,4,8,12

    float acc[4][4] = {};

    for (int k0 = 0; k0 < HDIM; k0 += PK_KC) {
        // load A tile (emb rows m0..m0+63)
        {
            int m = m0 + lm;
            int k = k0 + lk;
            float4 v = make_float4(0.f, 0.f, 0.f, 0.f);
            if (m < VOCAB) {
                if (k + 3 < HDIM) {
                    v = *reinterpret_cast<const float4*>(&emb[(size_t)m * HDIM + k]);
                } else {
                    float t0 = (k     < HDIM) ? emb[(size_t)m * HDIM + k    ] : 0.f;
                    float t1 = (k + 1 < HDIM) ? emb[(size_t)m * HDIM + k + 1] : 0.f;
                    float t2 = (k + 2 < HDIM) ? emb[(size_t)m * HDIM + k + 2] : 0.f;
                    float t3 = (k + 3 < HDIM) ? emb[(size_t)m * HDIM + k + 3] : 0.f;
                    v = make_float4(t0, t1, t2, t3);
                }
            }
            sA[lk    ][lm] = v.x;
            sA[lk + 1][lm] = v.y;
            sA[lk + 2][lm] = v.z;
            sA[lk + 3][lm] = v.w;
        }
        // load B tile (W_ih rows n0..n0+63)
        {
            int n = n0 + lm;
            int k = k0 + lk;
            float4 v = make_float4(0.f, 0.f, 0.f, 0.f);
            if (n < HDIM) {
                if (k + 3 < HDIM) {
                    v = *reinterpret_cast<const float4*>(&W_ih[n * HDIM + k]);
                } else {
                    float t0 = (k     < HDIM) ? W_ih[n * HDIM + k    ] : 0.f;
                    float t1 = (k + 1 < HDIM) ? W_ih[n * HDIM + k + 1] : 0.f;
                    float t2 = (k + 2 < HDIM) ? W_ih[n * HDIM + k + 2] : 0.f;
                    float t3 = (k + 3 < HDIM) ? W_ih[n * HDIM + k + 3] : 0.f;
                    v = make_float4(t0, t1, t2, t3);
                }
            }
            sB[lk    ][lm] = v.x;
            sB[lk + 1][lm] = v.y;
            sB[lk + 2][lm] = v.z;
            sB[lk + 3][lm] = v.w;
        }
        __syncthreads();

        #pragma unroll
        for (int kk = 0; kk < PK_KC; kk++) {
            float4 a4 = *reinterpret_cast<const float4*>(&sA[kk][ty * 4]);
            float4 b4 = *reinterpret_cast<const float4*>(&sB[kk][tx * 4]);
            float av[4] = {a4.x, a4.y, a4.z, a4.w};
            float bv[4] = {b4.x, b4.y, b4.z, b4.w};
            #pragma unroll
            for (int mi = 0; mi < 4; mi++)
                #pragma unroll
                for (int ni = 0; ni < 4; ni++)
                    acc[mi][ni] += av[mi] * bv[ni];
        }
        __syncthreads();
    }

    #pragma unroll
    for (int mi = 0; mi < 4; mi++) {
        int m = m0 + ty * 4 + mi;
        if (m >= VOCAB) continue;
        #pragma unroll
        for (int ni = 0; ni < 4; ni++) {
            int n = n0 + tx * 4 + ni;
            if (n < HDIM)
                g_proj[(size_t)m * HDIM + n] = acc[mi][ni] + b_ih[n] + b_hh[n];
        }
    }
}

// ---------------------------------------------------------------------------
// Kernel 2: the Elman recurrence.
// One 2-CTA cluster per batch element. Each CTA holds 150 rows of W_hh in SMEM
// (padded to 304 cols), computes relu(proj[x_t] + W_hh_half @ h) per step,
// exchanges its half of h with the peer CTA via DSMEM, and atomicMax-es into
// g_pooled. Warp layout: 4 k-groups x 8 rows -> 2 shfl.xor per row-reduce.
// ---------------------------------------------------------------------------
__global__ void __launch_bounds__(RNN_THREADS, 1) __cluster_dims__(2, 1, 1)
rnn_kernel(const int* __restrict__ x, const float* __restrict__ W_hh,
           float* __restrict__ out_hid)
{
    extern __shared__ float smem[];
    float* Wsh  = smem;                   // [HALF][HPAD]
    float* hbuf = smem + HALF * HPAD;     // [2][HPAD] double-buffered h

    const int tid = threadIdx.x;
    uint32_t rank;
    asm("mov.u32 %0, %%cluster_ctarank;" : "=r"(rank));
    const int batch = blockIdx.x >> 1;

    // Load this CTA's half of W_hh (rows [rank*150, rank*150+150)), zero-pad cols.
    for (int idx = tid; idx < HALF * HPAD; idx += RNN_THREADS) {
        int r = idx / HPAD;
        int c = idx - r * HPAD;
        Wsh[idx] = (c < HDIM) ? W_hh[(rank * HALF + r) * HDIM + c] : 0.f;
    }
    for (int idx = tid; idx < 2 * HPAD; idx += RNN_THREADS) hbuf[idx] = 0.f;  // h0 = 0
    __syncthreads();
    asm volatile("barrier.cluster.arrive.aligned;" ::: "memory");
    asm volatile("barrier.cluster.wait.aligned;"   ::: "memory");

    const int w = tid >> 5;
    const int l = tid & 31;
    const int g = l >> 3;        // k-group 0..3
    const int i = l & 7;         // row-sub 0..7
    const int r_loc = w * 8 + i; // 0..159 (150 valid)
    const bool valid = (r_loc < HALF);
    const int r_use = valid ? r_loc : 0;
    const int row_g = rank * HALF + r_use;   // global output row 0..299

    const float* wrow = Wsh + r_use * HPAD + g * GCHUNK;

    // Precompute local + peer SMEM addresses for the h exchange.
    uint32_t hbase;
    asm("{ .reg .u64 t; cvta.to.shared.u64 t, %1; cvt.u32.u64 %0, t; }"
        : "=r"(hbase) : "l"(hbuf));
    uint32_t ra[2];
    {
        uint32_t la0 = hbase + (uint32_t)row_g * 4u;
        uint32_t la1 = hbase + (uint32_t)(HPAD + row_g) * 4u;
        uint32_t pr = rank ^ 1u;
        asm("mapa.shared::cluster.u32 %0, %1, %2;" : "=r"(ra[0]) : "r"(la0), "r"(pr));
        asm("mapa.shared::cluster.u32 %0, %1, %2;" : "=r"(ra[1]) : "r"(la1), "r"(pr));
    }

    int p = 0;
    for (int s = 0; s < SLEN; s++) {
        // Fetch input projection early (latency hidden under the dot phase).
        float xpv = 0.f;
        if (g == 0 && valid) {
            int tok = __ldg(&x[s * BATCH + batch]);
            xpv = __ldg(&g_proj[(size_t)tok * HDIM + row_g]);
        }

        // 76-float chunk dot product with packed f32x2 FMA.
        const float* hsrc = hbuf + p * HPAD + g * GCHUNK;
        unsigned long long acc0 = 0ull, acc1 = 0ull;
        #pragma unroll
        for (int j = 0; j < NJ; j++) {
            ulonglong2 wv = *reinterpret_cast<const ulonglong2*>(wrow + j * 4);
            ulonglong2 hv = *reinterpret_cast<const ulonglong2*>(hsrc + j * 4);
            acc0 = fma2(wv.x, hv.x, acc0);
            acc1 = fma2(wv.y, hv.y, acc1);
        }
        unsigned long long accs;
        asm("add.rn.f32x2 %0, %1, %2;" : "=l"(accs) : "l"(acc0), "l"(acc1));
        float sum = __uint_as_float((uint32_t)accs) +
                    __uint_as_float((uint32_t)(accs >> 32));
        // reduce across the 4 k-groups (lanes strided by 8)
        sum += __shfl_xor_sync(0xffffffffu, sum, 8);
        sum += __shfl_xor_sync(0xffffffffu, sum, 16);

        const int pn = p ^ 1;
        if (g == 0 && valid) {
            float v = fmaxf(sum + xpv, 0.f);
            hbuf[pn * HPAD + row_g] = v;                                   // local
            asm volatile("st.shared::cluster.f32 [%0], %1;"                // peer
                         :: "r"(ra[pn]), "f"(v) : "memory");
            // relu output >= 0: int-max == float-max on nonnegative floats
            atomicMax((int*)&g_pooled[s * HDIM + row_g], __float_as_int(v));
            if (s == SLEN - 1) out_hid[batch * HDIM + row_g] = v;
        }

        asm volatile("barrier.cluster.arrive.aligned;" ::: "memory");
        asm volatile("barrier.cluster.wait.aligned;"   ::: "memory");
        p = pn;
    }
}

// ---------------------------------------------------------------------------
// Kernel 3: out[s, c] = pooled[s, :] . W_out[c, :] + b_out[c]   (one warp per s)
// ---------------------------------------------------------------------------
__global__ void out_kernel(const float* __restrict__ W_out,
                           const float* __restrict__ b_out,
                           float* __restrict__ out)
{
    int s = blockIdx.x;
    int l = threadIdx.x;
    float a0 = 0.f, a1 = 0.f;
    for (int h = l; h < HDIM; h += 32) {
        float pv = g_pooled[s * HDIM + h];
        a0 += pv * W_out[h];
        a1 += pv * W_out[HDIM + h];
    }
    #pragma unroll
    for (int o = 16; o > 0; o >>= 1) {
        a0 += __shfl_down_sync(0xffffffffu, a0, o);
        a1 += __shfl_down_sync(0xffffffffu, a1, o);
    }
    if (l == 0) {
        out[s * 2 + 0] = a0 + b_out[0];
        out[s * 2 + 1] = a1 + b_out[1];
    }
}

// ---------------------------------------------------------------------------
// Launch: zero -> proj GEMM -> sequential RNN (64 clusters) -> output GEMM.
// Output layout: out (2048*2 floats) followed by hT (64*300 floats).
// ---------------------------------------------------------------------------
extern "C" void kernel_launch(void* const* d_in, const int* in_sizes, int n_in,
                              void* d_out, int out_size)
{
    (void)in_sizes; (void)n_in; (void)out_size;
    const int*   x     = (const int*)  d_in[0];
    const float* emb   = (const float*)d_in[1];
    const float* W_ih  = (const float*)d_in[2];
    const float* W_hh  = (const float*)d_in[3];
    const float* b_ih  = (const float*)d_in[4];
    const float* b_hh  = (const float*)d_in[5];
    const float* W_out = (const float*)d_in[6];
    const float* b_out = (const float*)d_in[7];

    float* out     = (float*)d_out;
    float* out_hid = out + SLEN * 2;

    cudaFuncSetAttribute(rnn_kernel,
                         cudaFuncAttributeMaxDynamicSharedMemorySize, RNN_SMEM);

    zero_pooled_kernel<<<(SLEN * HDIM + 1023) / 1024, 1024>>>();
    proj_kernel<<<dim3((VOCAB + 63) / 64, (HDIM + 63) / 64), 256>>>(emb, W_ih, b_ih, b_hh);
    rnn_kernel<<<BATCH * 2, RNN_THREADS, RNN_SMEM>>>(x, W_hh, out_hid);
    out_kernel<<<SLEN, 32>>>(W_out, b_out, out);
}

// round 4
// speedup vs baseline: 2.5744x; 2.5744x over previous
#include <cuda_runtime.h>
#include <cstdint>

#define VOCAB 50257
#define SLEN  2048
#define BATCH 64
#define HDIM  300
#define HPAD  304
#define HALF  150
#define GCHUNK 76            // HPAD / 4 column-groups
#define NJ    19             // GCHUNK / 4 float4s per thread
#define RNN_THREADS 640      // 20 warps x 8 row-slots = 160 >= 150

// Scratch (device globals are the sanctioned allocation-free scratch).
__device__ float g_proj[(size_t)VOCAB * HDIM];   // ~60.3 MB, L2-resident during rnn
__device__ float g_pooled[SLEN * HDIM];

// ---------------------------------------------------------------------------
// packed f32x2 helpers (FFMA2 — only reachable via PTX on sm_103a)
// ---------------------------------------------------------------------------
__device__ __forceinline__ unsigned long long fma2(unsigned long long a,
                                                   unsigned long long b,
                                                   unsigned long long c) {
    unsigned long long d;
    asm("fma.rn.f32x2 %0, %1, %2, %3;" : "=l"(d) : "l"(a), "l"(b), "l"(c));
    return d;
}

// ---------------------------------------------------------------------------
// Kernel 0: zero the pooled max buffer (graph replays must re-zero it)
// ---------------------------------------------------------------------------
__global__ void zero_pooled_kernel() {
    int idx = blockIdx.x * blockDim.x + threadIdx.x;
    if (idx < SLEN * HDIM) g_pooled[idx] = 0.f;
}

// ---------------------------------------------------------------------------
// Kernel 1: proj[v, i] = sum_k emb[v,k] * W_ih[i,k] + b_ih[i] + b_hh[i]
// Classic 64x64 tiled fp32 GEMM, 4x4 micro-tiles, KC=16.
// ---------------------------------------------------------------------------
#define PK_KC 16
__global__ void __launch_bounds__(256)
proj_kernel(const float* __restrict__ emb, const float* __restrict__ W_ih,
            const float* __restrict__ b_ih, const float* __restrict__ b_hh)
{
    __shared__ float sA[PK_KC][68];   // [k][m]  (emb tile, transposed)
    __shared__ float sB[PK_KC][68];   // [k][n]  (W_ih tile, transposed)

    const int tid = threadIdx.x;
    const int tx = tid & 15;
    const int ty = tid >> 4;
    const int m0 = blockIdx.x * 64;
    const int n0 = blockIdx.y * 64;

    const int e  = tid * 4;      // each thread loads one float4 per tile
    const int lm = e >> 4;       // 0..63
    const int lk = e & 15;       // 0,4,8,12

    float acc[4][4] = {};

    for (int k0 = 0; k0 < HDIM; k0 += PK_KC) {
        // load A tile (emb rows m0..m0+63)
        {
            int m = m0 + lm;
            int k = k0 + lk;
            float4 v = make_float4(0.f, 0.f, 0.f, 0.f);
            if (m < VOCAB) {
                if (k + 3 < HDIM) {
                    v = *reinterpret_cast<const float4*>(&emb[(size_t)m * HDIM + k]);
                } else {
                    float t0 = (k     < HDIM) ? emb[(size_t)m * HDIM + k    ] : 0.f;
                    float t1 = (k + 1 < HDIM) ? emb[(size_t)m * HDIM + k + 1] : 0.f;
                    float t2 = (k + 2 < HDIM) ? emb[(size_t)m * HDIM + k + 2] : 0.f;
                    float t3 = (k + 3 < HDIM) ? emb[(size_t)m * HDIM + k + 3] : 0.f;
                    v = make_float4(t0, t1, t2, t3);
                }
            }
            sA[lk    ][lm] = v.x;
            sA[lk + 1][lm] = v.y;
            sA[lk + 2][lm] = v.z;
            sA[lk + 3][lm] = v.w;
        }
        // load B tile (W_ih rows n0..n0+63)
        {
            int n = n0 + lm;
            int k = k0 + lk;
            float4 v = make_float4(0.f, 0.f, 0.f, 0.f);
            if (n < HDIM) {
                if (k + 3 < HDIM) {
                    v = *reinterpret_cast<const float4*>(&W_ih[n * HDIM + k]);
                } else {
                    float t0 = (k     < HDIM) ? W_ih[n * HDIM + k    ] : 0.f;
                    float t1 = (k + 1 < HDIM) ? W_ih[n * HDIM + k + 1] : 0.f;
                    float t2 = (k + 2 < HDIM) ? W_ih[n * HDIM + k + 2] : 0.f;
                    float t3 = (k + 3 < HDIM) ? W_ih[n * HDIM + k + 3] : 0.f;
                    v = make_float4(t0, t1, t2, t3);
                }
            }
            sB[lk    ][lm] = v.x;
            sB[lk + 1][lm] = v.y;
            sB[lk + 2][lm] = v.z;
            sB[lk + 3][lm] = v.w;
        }
        __syncthreads();

        #pragma unroll
        for (int kk = 0; kk < PK_KC; kk++) {
            float4 a4 = *reinterpret_cast<const float4*>(&sA[kk][ty * 4]);
            float4 b4 = *reinterpret_cast<const float4*>(&sB[kk][tx * 4]);
            float av[4] = {a4.x, a4.y, a4.z, a4.w};
            float bv[4] = {b4.x, b4.y, b4.z, b4.w};
            #pragma unroll
            for (int mi = 0; mi < 4; mi++)
                #pragma unroll
                for (int ni = 0; ni < 4; ni++)
                    acc[mi][ni] += av[mi] * bv[ni];
        }
        __syncthreads();
    }

    #pragma unroll
    for (int mi = 0; mi < 4; mi++) {
        int m = m0 + ty * 4 + mi;
        if (m >= VOCAB) continue;
        #pragma unroll
        for (int ni = 0; ni < 4; ni++) {
            int n = n0 + tx * 4 + ni;
            if (n < HDIM)
                g_proj[(size_t)m * HDIM + n] = acc[mi][ni] + b_ih[n] + b_hh[n];
        }
    }
}

// ---------------------------------------------------------------------------
// Kernel 2: the Elman recurrence — W_hh register-resident.
// One 2-CTA cluster per batch element. Thread (warp w, lane l): column-group
// g = l>>3 (0..3), row-slot i = l&7, local row = w*8+i (150 valid / CTA).
// Each thread holds its 76 W_hh values in registers (19 x ulonglong2).
// Per step: 19 broadcast LDS.128 of h + 38 packed-f32x2 FMA, 2 shfl reduce,
// DSMEM h exchange with peer CTA, one cluster barrier.
// ---------------------------------------------------------------------------
__global__ void __launch_bounds__(RNN_THREADS, 1) __cluster_dims__(2, 1, 1)
rnn_kernel(const int* __restrict__ x, const float* __restrict__ W_hh,
           float* __restrict__ out_hid)
{
    __shared__ float hbuf[2 * HPAD];     // double-buffered h (pad cols stay 0)

    const int tid = threadIdx.x;
    uint32_t rank;
    asm("mov.u32 %0, %%cluster_ctarank;" : "=r"(rank));
    const int batch = blockIdx.x >> 1;

    const int w = tid >> 5;
    const int l = tid & 31;
    const int g = l >> 3;        // k-group 0..3
    const int i = l & 7;         // row-sub 0..7
    const int r_loc = w * 8 + i; // 0..159 (150 valid)
    const bool valid = (r_loc < HALF);
    const int r_use = valid ? r_loc : 0;
    const int row_g = rank * HALF + r_use;   // global output row 0..299

    // ---- load this thread's 76 W_hh values into registers (one-time) ----
    ulonglong2 wq[NJ];
    #pragma unroll
    for (int j = 0; j < NJ; j++) {
        const int c0 = g * GCHUNK + j * 4;
        float4 v = make_float4(0.f, 0.f, 0.f, 0.f);
        if (c0 < HDIM)   // only (g==3, j==18) is fully out of range; rows are 16B-aligned (300*4=1200)
            v = *reinterpret_cast<const float4*>(&W_hh[row_g * HDIM + c0]);
        ulonglong2 q;
        q.x = ((unsigned long long)__float_as_uint(v.y) << 32) | (unsigned long long)__float_as_uint(v.x);
        q.y = ((unsigned long long)__float_as_uint(v.w) << 32) | (unsigned long long)__float_as_uint(v.z);
        wq[j] = q;
    }

    for (int idx = tid; idx < 2 * HPAD; idx += RNN_THREADS) hbuf[idx] = 0.f;  // h0 = 0
    __syncthreads();
    asm volatile("barrier.cluster.arrive.aligned;" ::: "memory");
    asm volatile("barrier.cluster.wait.aligned;"   ::: "memory");

    // Precompute local + peer SMEM addresses for the h exchange.
    uint32_t hbase;
    asm("{ .reg .u64 t; cvta.to.shared.u64 t, %1; cvt.u32.u64 %0, t; }"
        : "=r"(hbase) : "l"(hbuf));
    uint32_t ra[2];
    {
        uint32_t la0 = hbase + (uint32_t)row_g * 4u;
        uint32_t la1 = hbase + (uint32_t)(HPAD + row_g) * 4u;
        uint32_t pr = rank ^ 1u;
        asm("mapa.shared::cluster.u32 %0, %1, %2;" : "=r"(ra[0]) : "r"(la0), "r"(pr));
        asm("mapa.shared::cluster.u32 %0, %1, %2;" : "=r"(ra[1]) : "r"(la1), "r"(pr));
    }

    const bool writer = (g == 0) && valid;
    int p = 0;
    #pragma unroll 1
    for (int s = 0; s < SLEN; s++) {
        // Fetch input projection early (latency hidden under the dot phase).
        float xpv = 0.f;
        if (writer) {
            int tok = __ldg(&x[s * BATCH + batch]);
            xpv = __ldg(&g_proj[(size_t)tok * HDIM + row_g]);
        }

        // 76-float chunk dot product: W from registers, h broadcast from SMEM.
        const ulonglong2* h2 =
            reinterpret_cast<const ulonglong2*>(hbuf + p * HPAD + g * GCHUNK);
        unsigned long long acc0 = 0ull, acc1 = 0ull;
        #pragma unroll
        for (int j = 0; j < NJ; j++) {
            ulonglong2 hv = h2[j];
            acc0 = fma2(wq[j].x, hv.x, acc0);
            acc1 = fma2(wq[j].y, hv.y, acc1);
        }
        unsigned long long accs;
        asm("add.rn.f32x2 %0, %1, %2;" : "=l"(accs) : "l"(acc0), "l"(acc1));
        float sum = __uint_as_float((uint32_t)accs) +
                    __uint_as_float((uint32_t)(accs >> 32));
        // reduce across the 4 k-groups (lanes strided by 8)
        sum += __shfl_xor_sync(0xffffffffu, sum, 8);
        sum += __shfl_xor_sync(0xffffffffu, sum, 16);

        const int pn = p ^ 1;
        if (writer) {
            float v = fmaxf(sum + xpv, 0.f);
            hbuf[pn * HPAD + row_g] = v;                                   // local
            asm volatile("st.shared::cluster.f32 [%0], %1;"                // peer
                         :: "r"(ra[pn]), "f"(v) : "memory");
            // relu output >= 0: int-max == float-max on nonnegative floats
            atomicMax((int*)&g_pooled[s * HDIM + row_g], __float_as_int(v));
            if (s == SLEN - 1) out_hid[batch * HDIM + row_g] = v;
        }

        asm volatile("barrier.cluster.arrive.aligned;" ::: "memory");
        asm volatile("barrier.cluster.wait.aligned;"   ::: "memory");
        p = pn;
    }
}

// ---------------------------------------------------------------------------
// Kernel 3: out[s, c] = pooled[s, :] . W_out[c, :] + b_out[c]   (one warp per s)
// ---------------------------------------------------------------------------
__global__ void out_kernel(const float* __restrict__ W_out,
                           const float* __restrict__ b_out,
                           float* __restrict__ out)
{
    int s = blockIdx.x;
    int l = threadIdx.x;
    float a0 = 0.f, a1 = 0.f;
    for (int h = l; h < HDIM; h += 32) {
        float pv = g_pooled[s * HDIM + h];
        a0 += pv * W_out[h];
        a1 += pv * W_out[HDIM + h];
    }
    #pragma unroll
    for (int o = 16; o > 0; o >>= 1) {
        a0 += __shfl_down_sync(0xffffffffu, a0, o);
        a1 += __shfl_down_sync(0xffffffffu, a1, o);
    }
    if (l == 0) {
        out[s * 2 + 0] = a0 + b_out[0];
        out[s * 2 + 1] = a1 + b_out[1];
    }
}

// ---------------------------------------------------------------------------
// Launch: zero -> proj GEMM -> sequential RNN (64 clusters) -> output GEMM.
// Output layout: out (2048*2 floats) followed by hT (64*300 floats).
// ---------------------------------------------------------------------------
extern "C" void kernel_launch(void* const* d_in, const int* in_sizes, int n_in,
                              void* d_out, int out_size)
{
    (void)in_sizes; (void)n_in; (void)out_size;
    const int*   x     = (const int*)  d_in[0];
    const float* emb   = (const float*)d_in[1];
    const float* W_ih  = (const float*)d_in[2];
    const float* W_hh  = (const float*)d_in[3];
    const float* b_ih  = (const float*)d_in[4];
    const float* b_hh  = (const float*)d_in[5];
    const float* W_out = (const float*)d_in[6];
    const float* b_out = (const float*)d_in[7];

    float* out     = (float*)d_out;
    float* out_hid = out + SLEN * 2;

    zero_pooled_kernel<<<(SLEN * HDIM + 1023) / 1024, 1024>>>();
    proj_kernel<<<dim3((VOCAB + 63) / 64, (HDIM + 63) / 64), 256>>>(emb, W_ih, b_ih, b_hh);
    rnn_kernel<<<BATCH * 2, RNN_THREADS>>>(x, W_hh, out_hid);
    out_kernel<<<SLEN, 32>>>(W_out, b_out, out);
}

// round 5
// speedup vs baseline: 3.1704x; 1.2315x over previous
#include <cuda_runtime.h>
#include <cstdint>

#define VOCAB 50257
#define SLEN  2048
#define BATCH 64
#define HDIM  300
#define HPAD  304
#define HALF  150
#define GCHUNK 76            // HPAD / 4 column-groups
#define NJ    19             // GCHUNK / 4 float4s per thread
#define RNN_THREADS 608      // 19 warps x 8 row-slots = 152 >= 150

// Scratch (device globals are the sanctioned allocation-free scratch).
__device__ float g_proj[(size_t)VOCAB * HDIM];   // ~60.3 MB
__device__ float g_pooled[SLEN * HDIM];

// ---------------------------------------------------------------------------
// packed f32x2 helpers (FFMA2 — only reachable via PTX on sm_103a)
// ---------------------------------------------------------------------------
__device__ __forceinline__ unsigned long long fma2(unsigned long long a,
                                                   unsigned long long b,
                                                   unsigned long long c) {
    unsigned long long d;
    asm("fma.rn.f32x2 %0, %1, %2, %3;" : "=l"(d) : "l"(a), "l"(b), "l"(c));
    return d;
}
__device__ __forceinline__ unsigned long long dup2(float a) {
    unsigned long long d;
    asm("mov.b64 %0, {%1, %1};" : "=l"(d) : "f"(a));
    return d;
}

// ---------------------------------------------------------------------------
// Kernel 0: zero the pooled max buffer (graph replays must re-zero it)
// ---------------------------------------------------------------------------
__global__ void zero_pooled_kernel() {
    int idx = blockIdx.x * blockDim.x + threadIdx.x;
    if (idx < SLEN * HDIM) g_pooled[idx] = 0.f;
}

// ---------------------------------------------------------------------------
// Kernel 1: proj[v, i] = sum_k emb[v,k] * W_ih[i,k] + b_ih[i] + b_hh[i]
// 64x64 tiled fp32 GEMM, 4x4 micro-tiles via packed f32x2 FMA, KC=16.
// ---------------------------------------------------------------------------
#define PK_KC 16
__global__ void __launch_bounds__(256)
proj_kernel(const float* __restrict__ emb, const float* __restrict__ W_ih,
            const float* __restrict__ b_ih, const float* __restrict__ b_hh)
{
    __shared__ float sA[PK_KC][68];   // [k][m]  (emb tile, transposed)
    __shared__ float sB[PK_KC][68];   // [k][n]  (W_ih tile, transposed)

    const int tid = threadIdx.x;
    const int tx = tid & 15;
    const int ty = tid >> 4;
    const int m0 = blockIdx.x * 64;
    const int n0 = blockIdx.y * 64;

    const int e  = tid * 4;      // each thread loads one float4 per tile
    const int lm = e >> 4;       // 0..63
    const int lk = e & 15;       // 0,4,8,12

    unsigned long long acc2[4][2] = {};

    for (int k0 = 0; k0 < HDIM; k0 += PK_KC) {
        // load A tile (emb rows m0..m0+63)
        {
            int m = m0 + lm;
            int k = k0 + lk;
            float4 v = make_float4(0.f, 0.f, 0.f, 0.f);
            if (m < VOCAB) {
                if (k + 3 < HDIM) {
                    v = *reinterpret_cast<const float4*>(&emb[(size_t)m * HDIM + k]);
                } else {
                    float t0 = (k     < HDIM) ? emb[(size_t)m * HDIM + k    ] : 0.f;
                    float t1 = (k + 1 < HDIM) ? emb[(size_t)m * HDIM + k + 1] : 0.f;
                    float t2 = (k + 2 < HDIM) ? emb[(size_t)m * HDIM + k + 2] : 0.f;
                    float t3 = (k + 3 < HDIM) ? emb[(size_t)m * HDIM + k + 3] : 0.f;
                    v = make_float4(t0, t1, t2, t3);
                }
            }
            sA[lk    ][lm] = v.x;
            sA[lk + 1][lm] = v.y;
            sA[lk + 2][lm] = v.z;
            sA[lk + 3][lm] = v.w;
        }
        // load B tile (W_ih rows n0..n0+63)
        {
            int n = n0 + lm;
            int k = k0 + lk;
            float4 v = make_float4(0.f, 0.f, 0.f, 0.f);
            if (n < HDIM) {
                if (k + 3 < HDIM) {
                    v = *reinterpret_cast<const float4*>(&W_ih[n * HDIM + k]);
                } else {
                    float t0 = (k     < HDIM) ? W_ih[n * HDIM + k    ] : 0.f;
                    float t1 = (k + 1 < HDIM) ? W_ih[n * HDIM + k + 1] : 0.f;
                    float t2 = (k + 2 < HDIM) ? W_ih[n * HDIM + k + 2] : 0.f;
                    float t3 = (k + 3 < HDIM) ? W_ih[n * HDIM + k + 3] : 0.f;
                    v = make_float4(t0, t1, t2, t3);
                }
            }
            sB[lk    ][lm] = v.x;
            sB[lk + 1][lm] = v.y;
            sB[lk + 2][lm] = v.z;
            sB[lk + 3][lm] = v.w;
        }
        __syncthreads();

        #pragma unroll
        for (int kk = 0; kk < PK_KC; kk++) {
            float4 a4 = *reinterpret_cast<const float4*>(&sA[kk][ty * 4]);
            ulonglong2 b2 = *reinterpret_cast<const ulonglong2*>(&sB[kk][tx * 4]);
            float av[4] = {a4.x, a4.y, a4.z, a4.w};
            #pragma unroll
            for (int mi = 0; mi < 4; mi++) {
                unsigned long long am = dup2(av[mi]);
                acc2[mi][0] = fma2(am, b2.x, acc2[mi][0]);
                acc2[mi][1] = fma2(am, b2.y, acc2[mi][1]);
            }
        }
        __syncthreads();
    }

    #pragma unroll
    for (int mi = 0; mi < 4; mi++) {
        int m = m0 + ty * 4 + mi;
        if (m >= VOCAB) continue;
        float r[4];
        r[0] = __uint_as_float((uint32_t)(acc2[mi][0]));
        r[1] = __uint_as_float((uint32_t)(acc2[mi][0] >> 32));
        r[2] = __uint_as_float((uint32_t)(acc2[mi][1]));
        r[3] = __uint_as_float((uint32_t)(acc2[mi][1] >> 32));
        #pragma unroll
        for (int ni = 0; ni < 4; ni++) {
            int n = n0 + tx * 4 + ni;
            if (n < HDIM)
                g_proj[(size_t)m * HDIM + n] = r[ni] + b_ih[n] + b_hh[n];
        }
    }
}

// ---------------------------------------------------------------------------
// Kernel 2: the Elman recurrence — W_hh register-resident + gather prefetch.
// One 2-CTA cluster per batch element. Thread (warp w, lane l): column-group
// g = l>>3 (0..3), row-slot i = l&7, local row = w*8+i (150 valid / CTA).
// Each thread holds its 76 W_hh values in registers (19 x ulonglong2).
// Per step: 19 broadcast LDS.128 of h + 38 packed-f32x2 FMA, 2 shfl reduce,
// DSMEM h exchange with peer CTA, one cluster barrier. The token/proj gather
// for the NEXT steps plus the pooled atomicMax run in the arrive->wait shadow.
// ---------------------------------------------------------------------------
__global__ void __launch_bounds__(RNN_THREADS, 1) __cluster_dims__(2, 1, 1)
rnn_kernel(const int* __restrict__ x, const float* __restrict__ W_hh,
           float* __restrict__ out_hid)
{
    __shared__ float hbuf[2 * HPAD];     // double-buffered h (pad cols stay 0)

    const int tid = threadIdx.x;
    uint32_t rank;
    asm("mov.u32 %0, %%cluster_ctarank;" : "=r"(rank));
    const int batch = blockIdx.x >> 1;

    const int w = tid >> 5;
    const int l = tid & 31;
    const int g = l >> 3;        // k-group 0..3
    const int i = l & 7;         // row-sub 0..7
    const int r_loc = w * 8 + i; // 0..151 (150 valid)
    const bool valid = (r_loc < HALF);
    const int r_use = valid ? r_loc : 0;
    const int row_g = rank * HALF + r_use;   // global output row 0..299

    // ---- load this thread's 76 W_hh values into registers (one-time) ----
    ulonglong2 wq[NJ];
    #pragma unroll
    for (int j = 0; j < NJ; j++) {
        const int c0 = g * GCHUNK + j * 4;
        float4 v = make_float4(0.f, 0.f, 0.f, 0.f);
        if (c0 < HDIM)   // only (g==3, j==18) is fully out of range; rows are 16B-aligned
            v = *reinterpret_cast<const float4*>(&W_hh[row_g * HDIM + c0]);
        ulonglong2 q;
        q.x = ((unsigned long long)__float_as_uint(v.y) << 32) | (unsigned long long)__float_as_uint(v.x);
        q.y = ((unsigned long long)__float_as_uint(v.w) << 32) | (unsigned long long)__float_as_uint(v.z);
        wq[j] = q;
    }

    for (int idx = tid; idx < 2 * HPAD; idx += RNN_THREADS) hbuf[idx] = 0.f;  // h0 = 0
    __syncthreads();
    asm volatile("barrier.cluster.arrive.aligned;" ::: "memory");
    asm volatile("barrier.cluster.wait.aligned;"   ::: "memory");

    // Precompute local + peer SMEM addresses for the h exchange.
    uint32_t hbase;
    asm("{ .reg .u64 t; cvta.to.shared.u64 t, %1; cvt.u32.u64 %0, t; }"
        : "=r"(hbase) : "l"(hbuf));
    uint32_t ra[2];
    {
        uint32_t la0 = hbase + (uint32_t)row_g * 4u;
        uint32_t la1 = hbase + (uint32_t)(HPAD + row_g) * 4u;
        uint32_t pr = rank ^ 1u;
        asm("mapa.shared::cluster.u32 %0, %1, %2;" : "=r"(ra[0]) : "r"(la0), "r"(pr));
        asm("mapa.shared::cluster.u32 %0, %1, %2;" : "=r"(ra[1]) : "r"(la1), "r"(pr));
    }

    const bool writer = (g == 0) && valid;

    // ---- gather pipeline prologue: xpv for step 0, token for step 1 ----
    float xpv_c = 0.f;
    int tok_n = 0;
    if (writer) {
        int t0 = __ldg(&x[batch]);                        // token for s=0
        xpv_c = __ldg(&g_proj[(size_t)t0 * HDIM + row_g]);
        tok_n = __ldg(&x[BATCH + batch]);                 // token for s=1
    }

    int p = 0;
    #pragma unroll 1
    for (int s = 0; s < SLEN; s++) {
        // 76-float chunk dot product: W from registers, h broadcast from SMEM.
        const ulonglong2* h2 =
            reinterpret_cast<const ulonglong2*>(hbuf + p * HPAD + g * GCHUNK);
        unsigned long long acc0 = 0ull, acc1 = 0ull;
        #pragma unroll
        for (int j = 0; j < NJ; j++) {
            ulonglong2 hv = h2[j];
            acc0 = fma2(wq[j].x, hv.x, acc0);
            acc1 = fma2(wq[j].y, hv.y, acc1);
        }
        unsigned long long accs;
        asm("add.rn.f32x2 %0, %1, %2;" : "=l"(accs) : "l"(acc0), "l"(acc1));
        float sum = __uint_as_float((uint32_t)accs) +
                    __uint_as_float((uint32_t)(accs >> 32));
        // reduce across the 4 k-groups (lanes strided by 8)
        sum += __shfl_xor_sync(0xffffffffu, sum, 8);
        sum += __shfl_xor_sync(0xffffffffu, sum, 16);

        const int pn = p ^ 1;
        float v = 0.f;
        if (writer) {
            v = fmaxf(sum + xpv_c, 0.f);
            hbuf[pn * HPAD + row_g] = v;                                   // local
            asm volatile("st.shared::cluster.f32 [%0], %1;"                // peer
                         :: "r"(ra[pn]), "f"(v) : "memory");
        }

        asm volatile("barrier.cluster.arrive.aligned;" ::: "memory");

        // ---- latency shadow: prefetch next gather, drain pooled max ----
        if (writer) {
            xpv_c = __ldg(&g_proj[(size_t)tok_n * HDIM + row_g]);  // for s+1
            int s2 = (s + 2 < SLEN) ? (s + 2) : (SLEN - 1);
            tok_n = __ldg(&x[s2 * BATCH + batch]);                 // for s+2
            // relu output >= 0: int-max == float-max on nonnegative floats
            atomicMax((int*)&g_pooled[s * HDIM + row_g], __float_as_int(v));
            if (s == SLEN - 1) out_hid[batch * HDIM + row_g] = v;
        }

        asm volatile("barrier.cluster.wait.aligned;"   ::: "memory");
        p = pn;
    }
}

// ---------------------------------------------------------------------------
// Kernel 3: out[s, c] = pooled[s, :] . W_out[c, :] + b_out[c]   (one warp per s)
// ---------------------------------------------------------------------------
__global__ void out_kernel(const float* __restrict__ W_out,
                           const float* __restrict__ b_out,
                           float* __restrict__ out)
{
    int s = blockIdx.x;
    int l = threadIdx.x;
    float a0 = 0.f, a1 = 0.f;
    for (int h = l; h < HDIM; h += 32) {
        float pv = g_pooled[s * HDIM + h];
        a0 += pv * W_out[h];
        a1 += pv * W_out[HDIM + h];
    }
    #pragma unroll
    for (int o = 16; o > 0; o >>= 1) {
        a0 += __shfl_down_sync(0xffffffffu, a0, o);
        a1 += __shfl_down_sync(0xffffffffu, a1, o);
    }
    if (l == 0) {
        out[s * 2 + 0] = a0 + b_out[0];
        out[s * 2 + 1] = a1 + b_out[1];
    }
}

// ---------------------------------------------------------------------------
// Launch: zero -> proj GEMM -> sequential RNN (64 clusters) -> output GEMM.
// Output layout: out (2048*2 floats) followed by hT (64*300 floats).
// ---------------------------------------------------------------------------
extern "C" void kernel_launch(void* const* d_in, const int* in_sizes, int n_in,
                              void* d_out, int out_size)
{
    (void)in_sizes; (void)n_in; (void)out_size;
    const int*   x     = (const int*)  d_in[0];
    const float* emb   = (const float*)d_in[1];
    const float* W_ih  = (const float*)d_in[2];
    const float* W_hh  = (const float*)d_in[3];
    const float* b_ih  = (const float*)d_in[4];
    const float* b_hh  = (const float*)d_in[5];
    const float* W_out = (const float*)d_in[6];
    const float* b_out = (const float*)d_in[7];

    float* out     = (float*)d_out;
    float* out_hid = out + SLEN * 2;

    zero_pooled_kernel<<<(SLEN * HDIM + 1023) / 1024, 1024>>>();
    proj_kernel<<<dim3((VOCAB + 63) / 64, (HDIM + 63) / 64), 256>>>(emb, W_ih, b_ih, b_hh);
    rnn_kernel<<<BATCH * 2, RNN_THREADS>>>(x, W_hh, out_hid);
    out_kernel<<<SLEN, 32>>>(W_out, b_out, out);
}

// round 6
// speedup vs baseline: 3.4638x; 1.0926x over previous
#include <cuda_runtime.h>
#include <cstdint>

#define VOCAB 50257
#define SLEN  2048
#define BATCH 64
#define HDIM  300
#define HPAD  304
#define HALF  150
#define GCHUNK 76            // HPAD / 4 column-groups
#define NJ    19             // GCHUNK / 4 float4s per thread
#define RNN_THREADS 608      // 19 warps x 8 row-slots = 152 >= 150

// Scratch (device globals are the sanctioned allocation-free scratch).
__device__ float g_proj[(size_t)VOCAB * HDIM];   // ~60.3 MB
__device__ float g_pooled[SLEN * HDIM];

// ---------------------------------------------------------------------------
// packed f32x2 helpers (FFMA2 — only reachable via PTX on sm_103a)
// ---------------------------------------------------------------------------
__device__ __forceinline__ unsigned long long fma2(unsigned long long a,
                                                   unsigned long long b,
                                                   unsigned long long c) {
    unsigned long long d;
    asm("fma.rn.f32x2 %0, %1, %2, %3;" : "=l"(d) : "l"(a), "l"(b), "l"(c));
    return d;
}
__device__ __forceinline__ unsigned long long dup2(float a) {
    unsigned long long d;
    asm("mov.b64 %0, {%1, %1};" : "=l"(d) : "f"(a));
    return d;
}

// ---------------------------------------------------------------------------
// Kernel 0: zero the pooled max buffer (graph replays must re-zero it)
// ---------------------------------------------------------------------------
__global__ void zero_pooled_kernel() {
    int idx = blockIdx.x * blockDim.x + threadIdx.x;
    if (idx < SLEN * HDIM) g_pooled[idx] = 0.f;
}

// ---------------------------------------------------------------------------
// Kernel 1: proj[v, i] = sum_k emb[v,k] * W_ih[i,k] + b_ih[i] + b_hh[i]
// 64x64 tiled fp32 GEMM, 4x4 micro-tiles via packed f32x2 FMA, KC=16.
// ---------------------------------------------------------------------------
#define PK_KC 16
__global__ void __launch_bounds__(256)
proj_kernel(const float* __restrict__ emb, const float* __restrict__ W_ih,
            const float* __restrict__ b_ih, const float* __restrict__ b_hh)
{
    __shared__ float sA[PK_KC][68];   // [k][m]  (emb tile, transposed)
    __shared__ float sB[PK_KC][68];   // [k][n]  (W_ih tile, transposed)

    const int tid = threadIdx.x;
    const int tx = tid & 15;
    const int ty = tid >> 4;
    const int m0 = blockIdx.x * 64;
    const int n0 = blockIdx.y * 64;

    const int e  = tid * 4;      // each thread loads one float4 per tile
    const int lm = e >> 4;       // 0..63
    const int lk = e & 15;       // 0,4,8,12

    unsigned long long acc2[4][2] = {};

    for (int k0 = 0; k0 < HDIM; k0 += PK_KC) {
        // load A tile (emb rows m0..m0+63)
        {
            int m = m0 + lm;
            int k = k0 + lk;
            float4 v = make_float4(0.f, 0.f, 0.f, 0.f);
            if (m < VOCAB) {
                if (k + 3 < HDIM) {
                    v = *reinterpret_cast<const float4*>(&emb[(size_t)m * HDIM + k]);
                } else {
                    float t0 = (k     < HDIM) ? emb[(size_t)m * HDIM + k    ] : 0.f;
                    float t1 = (k + 1 < HDIM) ? emb[(size_t)m * HDIM + k + 1] : 0.f;
                    float t2 = (k + 2 < HDIM) ? emb[(size_t)m * HDIM + k + 2] : 0.f;
                    float t3 = (k + 3 < HDIM) ? emb[(size_t)m * HDIM + k + 3] : 0.f;
                    v = make_float4(t0, t1, t2, t3);
                }
            }
            sA[lk    ][lm] = v.x;
            sA[lk + 1][lm] = v.y;
            sA[lk + 2][lm] = v.z;
            sA[lk + 3][lm] = v.w;
        }
        // load B tile (W_ih rows n0..n0+63)
        {
            int n = n0 + lm;
            int k = k0 + lk;
            float4 v = make_float4(0.f, 0.f, 0.f, 0.f);
            if (n < HDIM) {
                if (k + 3 < HDIM) {
                    v = *reinterpret_cast<const float4*>(&W_ih[n * HDIM + k]);
                } else {
                    float t0 = (k     < HDIM) ? W_ih[n * HDIM + k    ] : 0.f;
                    float t1 = (k + 1 < HDIM) ? W_ih[n * HDIM + k + 1] : 0.f;
                    float t2 = (k + 2 < HDIM) ? W_ih[n * HDIM + k + 2] : 0.f;
                    float t3 = (k + 3 < HDIM) ? W_ih[n * HDIM + k + 3] : 0.f;
                    v = make_float4(t0, t1, t2, t3);
                }
            }
            sB[lk    ][lm] = v.x;
            sB[lk + 1][lm] = v.y;
            sB[lk + 2][lm] = v.z;
            sB[lk + 3][lm] = v.w;
        }
        __syncthreads();

        #pragma unroll
        for (int kk = 0; kk < PK_KC; kk++) {
            float4 a4 = *reinterpret_cast<const float4*>(&sA[kk][ty * 4]);
            ulonglong2 b2 = *reinterpret_cast<const ulonglong2*>(&sB[kk][tx * 4]);
            float av[4] = {a4.x, a4.y, a4.z, a4.w};
            #pragma unroll
            for (int mi = 0; mi < 4; mi++) {
                unsigned long long am = dup2(av[mi]);
                acc2[mi][0] = fma2(am, b2.x, acc2[mi][0]);
                acc2[mi][1] = fma2(am, b2.y, acc2[mi][1]);
            }
        }
        __syncthreads();
    }

    #pragma unroll
    for (int mi = 0; mi < 4; mi++) {
        int m = m0 + ty * 4 + mi;
        if (m >= VOCAB) continue;
        float r[4];
        r[0] = __uint_as_float((uint32_t)(acc2[mi][0]));
        r[1] = __uint_as_float((uint32_t)(acc2[mi][0] >> 32));
        r[2] = __uint_as_float((uint32_t)(acc2[mi][1]));
        r[3] = __uint_as_float((uint32_t)(acc2[mi][1] >> 32));
        #pragma unroll
        for (int ni = 0; ni < 4; ni++) {
            int n = n0 + tx * 4 + ni;
            if (n < HDIM)
                g_proj[(size_t)m * HDIM + n] = r[ni] + b_ih[n] + b_hh[n];
        }
    }
}

// ---------------------------------------------------------------------------
// Kernel 2: the Elman recurrence — W_hh register-resident, mbarrier handshake.
// One 2-CTA cluster per batch element. Thread (warp w, lane l): column-group
// g = l>>3 (0..3), row-slot i = l&7, local row = w*8+i (150 valid / CTA).
// Per step: 19 broadcast LDS.128 of h + 38 packed-f32x2 FMA, 2 shfl reduce,
// h exchange via st.shared::cluster, then a 1-arrival DSMEM mbarrier
// handshake (bar.sync -> arrive.release on peer's mbar -> shadow work ->
// try_wait.acquire on local mbar) instead of the heavyweight cluster barrier.
// ---------------------------------------------------------------------------
__global__ void __launch_bounds__(RNN_THREADS, 1) __cluster_dims__(2, 1, 1)
rnn_kernel(const int* __restrict__ x, const float* __restrict__ W_hh,
           float* __restrict__ out_hid)
{
    __shared__ float hbuf[2 * HPAD];            // double-buffered h (pads stay 0)
    __shared__ __align__(8) unsigned long long mbar;  // 1 arrival per phase

    const int tid = threadIdx.x;
    uint32_t rank;
    asm("mov.u32 %0, %%cluster_ctarank;" : "=r"(rank));
    const int batch = blockIdx.x >> 1;

    const int w = tid >> 5;
    const int l = tid & 31;
    const int g = l >> 3;        // k-group 0..3
    const int i = l & 7;         // row-sub 0..7
    const int r_loc = w * 8 + i; // 0..151 (150 valid)
    const bool valid = (r_loc < HALF);
    const int r_use = valid ? r_loc : 0;
    const int row_g = rank * HALF + r_use;   // global output row 0..299

    // ---- load this thread's 76 W_hh values into registers (one-time) ----
    ulonglong2 wq[NJ];
    #pragma unroll
    for (int j = 0; j < NJ; j++) {
        const int c0 = g * GCHUNK + j * 4;
        float4 v = make_float4(0.f, 0.f, 0.f, 0.f);
        if (c0 < HDIM)   // only (g==3, j==18) is fully out of range; rows are 16B-aligned
            v = *reinterpret_cast<const float4*>(&W_hh[row_g * HDIM + c0]);
        ulonglong2 q;
        q.x = ((unsigned long long)__float_as_uint(v.y) << 32) | (unsigned long long)__float_as_uint(v.x);
        q.y = ((unsigned long long)__float_as_uint(v.w) << 32) | (unsigned long long)__float_as_uint(v.z);
        wq[j] = q;
    }

    for (int idx = tid; idx < 2 * HPAD; idx += RNN_THREADS) hbuf[idx] = 0.f;  // h0 = 0

    // SMEM addresses (32-bit) for hbuf and the mbarrier.
    uint32_t hbase, mbaddr;
    asm("{ .reg .u64 t; cvta.to.shared.u64 t, %1; cvt.u32.u64 %0, t; }"
        : "=r"(hbase) : "l"(hbuf));
    asm("{ .reg .u64 t; cvta.to.shared.u64 t, %1; cvt.u32.u64 %0, t; }"
        : "=r"(mbaddr) : "l"(&mbar));

    if (tid == 0) {
        asm volatile("mbarrier.init.shared.b64 [%0], 1;" :: "r"(mbaddr) : "memory");
    }
    __syncthreads();
    // Both CTAs' hbuf zeros + mbarrier init must be visible cluster-wide once.
    asm volatile("barrier.cluster.arrive.aligned;" ::: "memory");
    asm volatile("barrier.cluster.wait.aligned;"   ::: "memory");

    // Peer addresses: h slots (both phases) and the peer's mbarrier.
    const uint32_t pr = rank ^ 1u;
    uint32_t ra[2], peer_mbar;
    {
        uint32_t la0 = hbase + (uint32_t)row_g * 4u;
        uint32_t la1 = hbase + (uint32_t)(HPAD + row_g) * 4u;
        asm("mapa.shared::cluster.u32 %0, %1, %2;" : "=r"(ra[0]) : "r"(la0), "r"(pr));
        asm("mapa.shared::cluster.u32 %0, %1, %2;" : "=r"(ra[1]) : "r"(la1), "r"(pr));
        asm("mapa.shared::cluster.u32 %0, %1, %2;" : "=r"(peer_mbar) : "r"(mbaddr), "r"(pr));
    }

    const bool writer = (g == 0) && valid;

    // ---- gather pipeline prologue: xpv for step 0, token for step 1 ----
    float xpv_c = 0.f;
    int tok_n = 0;
    if (writer) {
        int t0 = __ldg(&x[batch]);                        // token for s=0
        xpv_c = __ldg(&g_proj[(size_t)t0 * HDIM + row_g]);
        tok_n = __ldg(&x[BATCH + batch]);                 // token for s=1
    }

    int p = 0;
    #pragma unroll 1
    for (int s = 0; s < SLEN; s++) {
        // 76-float chunk dot product: W from registers, h broadcast from SMEM.
        const ulonglong2* h2 =
            reinterpret_cast<const ulonglong2*>(hbuf + p * HPAD + g * GCHUNK);
        unsigned long long acc0 = 0ull, acc1 = 0ull;
        #pragma unroll
        for (int j = 0; j < NJ; j++) {
            ulonglong2 hv = h2[j];
            acc0 = fma2(wq[j].x, hv.x, acc0);
            acc1 = fma2(wq[j].y, hv.y, acc1);
        }
        unsigned long long accs;
        asm("add.rn.f32x2 %0, %1, %2;" : "=l"(accs) : "l"(acc0), "l"(acc1));
        float sum = __uint_as_float((uint32_t)accs) +
                    __uint_as_float((uint32_t)(accs >> 32));
        // reduce across the 4 k-groups (lanes strided by 8)
        sum += __shfl_xor_sync(0xffffffffu, sum, 8);
        sum += __shfl_xor_sync(0xffffffffu, sum, 16);

        const int pn = p ^ 1;
        float v = 0.f;
        if (writer) {
            v = fmaxf(sum + xpv_c, 0.f);
            hbuf[pn * HPAD + row_g] = v;                                   // local
            asm volatile("st.shared::cluster.f32 [%0], %1;"                // peer
                         :: "r"(ra[pn]), "f"(v) : "memory");
        }

        // All reads of hbuf[p] and all peer-stores from this CTA are done.
        __syncthreads();
        if (tid == 0) {
            asm volatile(
                "mbarrier.arrive.release.cluster.shared::cluster.b64 _, [%0];"
                :: "r"(peer_mbar) : "memory");
        }

        // ---- latency shadow: prefetch next gather, drain pooled max ----
        if (writer) {
            xpv_c = __ldg(&g_proj[(size_t)tok_n * HDIM + row_g]);  // for s+1
            int s2 = (s + 2 < SLEN) ? (s + 2) : (SLEN - 1);
            tok_n = __ldg(&x[s2 * BATCH + batch]);                 // for s+2
            // relu output >= 0: int-max == float-max on nonnegative floats
            atomicMax((int*)&g_pooled[s * HDIM + row_g], __float_as_int(v));
            if (s == SLEN - 1) out_hid[batch * HDIM + row_g] = v;
        }

        // Wait for the peer's arrive (acquire: makes its h stores visible).
        {
            const uint32_t ph = (uint32_t)(s & 1);
            uint32_t done;
            asm volatile(
                "{\n\t.reg .pred p;\n\t"
                "mbarrier.try_wait.parity.acquire.cluster.shared::cta.b64 p, [%1], %2;\n\t"
                "selp.b32 %0, 1, 0, p;\n\t}"
                : "=r"(done) : "r"(mbaddr), "r"(ph) : "memory");
            if (!done) {
                asm volatile(
                    "{\n\t.reg .pred P1;\n\t"
                    "WAIT_LOOP_%=:\n\t"
                    "mbarrier.try_wait.parity.acquire.cluster.shared::cta.b64 P1, [%0], %1, 0x989680;\n\t"
                    "@P1 bra.uni WAIT_DONE_%=;\n\t"
                    "bra.uni WAIT_LOOP_%=;\n\t"
                    "WAIT_DONE_%=:\n\t}"
                    :: "r"(mbaddr), "r"(ph) : "memory");
            }
        }
        p = pn;
    }
}

// ---------------------------------------------------------------------------
// Kernel 3: out[s, c] = pooled[s, :] . W_out[c, :] + b_out[c]   (one warp per s)
// ---------------------------------------------------------------------------
__global__ void out_kernel(const float* __restrict__ W_out,
                           const float* __restrict__ b_out,
                           float* __restrict__ out)
{
    int s = blockIdx.x;
    int l = threadIdx.x;
    float a0 = 0.f, a1 = 0.f;
    for (int h = l; h < HDIM; h += 32) {
        float pv = g_pooled[s * HDIM + h];
        a0 += pv * W_out[h];
        a1 += pv * W_out[HDIM + h];
    }
    #pragma unroll
    for (int o = 16; o > 0; o >>= 1) {
        a0 += __shfl_down_sync(0xffffffffu, a0, o);
        a1 += __shfl_down_sync(0xffffffffu, a1, o);
    }
    if (l == 0) {
        out[s * 2 + 0] = a0 + b_out[0];
        out[s * 2 + 1] = a1 + b_out[1];
    }
}

// ---------------------------------------------------------------------------
// Launch: zero -> proj GEMM -> sequential RNN (64 clusters) -> output GEMM.
// Output layout: out (2048*2 floats) followed by hT (64*300 floats).
// ---------------------------------------------------------------------------
extern "C" void kernel_launch(void* const* d_in, const int* in_sizes, int n_in,
                              void* d_out, int out_size)
{
    (void)in_sizes; (void)n_in; (void)out_size;
    const int*   x     = (const int*)  d_in[0];
    const float* emb   = (const float*)d_in[1];
    const float* W_ih  = (const float*)d_in[2];
    const float* W_hh  = (const float*)d_in[3];
    const float* b_ih  = (const float*)d_in[4];
    const float* b_hh  = (const float*)d_in[5];
    const float* W_out = (const float*)d_in[6];
    const float* b_out = (const float*)d_in[7];

    float* out     = (float*)d_out;
    float* out_hid = out + SLEN * 2;

    zero_pooled_kernel<<<(SLEN * HDIM + 1023) / 1024, 1024>>>();
    proj_kernel<<<dim3((VOCAB + 63) / 64, (HDIM + 63) / 64), 256>>>(emb, W_ih, b_ih, b_hh);
    rnn_kernel<<<BATCH * 2, RNN_THREADS>>>(x, W_hh, out_hid);
    out_kernel<<<SLEN, 32>>>(W_out, b_out, out);
}